// round 1
// baseline (speedup 1.0000x reference)
#include <cuda_runtime.h>

// ---------------------------------------------------------------------------
// Sup_CCL_Loss: fused MLP embed (640->128 relu 128->128, L2 norm) for global
// and patch streams, then symmetric-KL losses (dil, dcl).
// Strategy: fp32 SGEMM with packed fma.rn.f32x2 (full-rate fp32 on sm_103a),
// both layers fused in one kernel (H resident in SMEM), fused norm epilogue.
// ---------------------------------------------------------------------------

#define T_KD   4.0f
#define Bsz    4096
#define Pn     12
#define DIN    640
#define Dm     128

#define BM     128
#define BK     16
#define NBLK_G (Bsz / BM)          // 32
#define NBLK_P (Pn * Bsz / BM)     // 384
#define HS_STRIDE 132
#define SMEM_FLOATS (128 * HS_STRIDE + 2 * BK * 128)
#define SMEM_BYTES  (SMEM_FLOATS * 4)

// Scratch (static device arrays: allowed; no cudaMalloc anywhere)
__device__ float g_buf[Bsz * Dm];
__device__ float p_buf[Pn * Bsz * Dm];
__device__ float part_dil[Bsz];
__device__ float part_dcl[Bsz];

typedef unsigned long long u64;

__device__ __forceinline__ u64 dup2(float v) {
    u64 r; asm("mov.b64 %0,{%1,%1};" : "=l"(r) : "f"(v)); return r;
}
__device__ __forceinline__ u64 pack2(float lo, float hi) {
    u64 r; asm("mov.b64 %0,{%1,%2};" : "=l"(r) : "f"(lo), "f"(hi)); return r;
}
__device__ __forceinline__ void unpack2(u64 v, float& lo, float& hi) {
    asm("mov.b64 {%0,%1},%2;" : "=f"(lo), "=f"(hi) : "l"(v));
}
__device__ __forceinline__ void fma2(u64& d, u64 a, u64 b) {
    asm("fma.rn.f32x2 %0,%1,%2,%3;" : "=l"(d) : "l"(a), "l"(b), "l"(d));
}

// one k-step of the 8x8 (as 8x4 packed) outer product
#define MMA_STEP(A0, A1, B0, B1) do {                                        \
    u64 bp0 = pack2((B0).x, (B0).y), bp1 = pack2((B0).z, (B0).w);            \
    u64 bp2 = pack2((B1).x, (B1).y), bp3 = pack2((B1).z, (B1).w);            \
    float av[8] = {(A0).x,(A0).y,(A0).z,(A0).w,(A1).x,(A1).y,(A1).z,(A1).w}; \
    _Pragma("unroll")                                                        \
    for (int ii = 0; ii < 8; ii++) {                                         \
        u64 ad = dup2(av[ii]);                                               \
        fma2(acc[ii][0], ad, bp0); fma2(acc[ii][1], ad, bp1);                \
        fma2(acc[ii][2], ad, bp2); fma2(acc[ii][3], ad, bp3);                \
    }                                                                        \
} while (0)

// transpose-store a 2x float4 strip (k-major tile [BK][128])
__device__ __forceinline__ void stile(float* S, float4 a, float4 b, int kb, int r) {
    S[(kb + 0) * 128 + r] = a.x; S[(kb + 1) * 128 + r] = a.y;
    S[(kb + 2) * 128 + r] = a.z; S[(kb + 3) * 128 + r] = a.w;
    S[(kb + 4) * 128 + r] = b.x; S[(kb + 5) * 128 + r] = b.y;
    S[(kb + 6) * 128 + r] = b.z; S[(kb + 7) * 128 + r] = b.w;
}

__global__ void __launch_bounds__(256, 2) embed_kernel(
    const float* __restrict__ ebg, const float* __restrict__ ebp,
    const float* __restrict__ gw1, const float* __restrict__ gb1,
    const float* __restrict__ gw2, const float* __restrict__ gb2,
    const float* __restrict__ pw1, const float* __restrict__ pb1,
    const float* __restrict__ pw2, const float* __restrict__ pb2)
{
    extern __shared__ float sm[];
    float* Hs = sm;                       // [128][132], k-major, block-swizzled
    float* Xs = sm + 128 * HS_STRIDE;     // [BK][128]
    float* Ws = Xs + BK * 128;            // [BK][128]
    float* red  = Xs;                     // reuse, stride 17
    float* rinv = Xs + 128 * 17;          // reuse

    const int blk = blockIdx.x;
    const float *X, *W1, *B1, *W2, *B2;
    float* OUT;
    int rowbase;
    if (blk < NBLK_G) {
        X = ebg; W1 = gw1; B1 = gb1; W2 = gw2; B2 = gb2;
        OUT = g_buf; rowbase = blk * BM;
    } else {
        X = ebp; W1 = pw1; B1 = pb1; W2 = pw2; B2 = pb2;
        OUT = p_buf; rowbase = (blk - NBLK_G) * BM;
    }

    const int t  = threadIdx.x;
    const int tx = t & 15;
    const int ty = t >> 4;
    const int row2 = t >> 1;          // 0..127 (loader row)
    const int kb   = (t & 1) * 8;     // loader k-offset

    u64 acc[8][4];
#pragma unroll
    for (int i = 0; i < 8; i++)
#pragma unroll
        for (int j = 0; j < 4; j++) acc[i][j] = 0ULL;

    // ---------------- Phase A: H = relu(X @ W1^T + b1), K = 640 -------------
    const float* xrow = X  + (size_t)(rowbase + row2) * DIN + kb;
    const float* wrow = W1 + (size_t)row2 * DIN + kb;
    float4 xa = *(const float4*)xrow, xb = *(const float4*)(xrow + 4);
    float4 wa = *(const float4*)wrow, wb = *(const float4*)(wrow + 4);

    for (int c = 0; c < DIN / BK; c++) {
        __syncthreads();
        stile(Xs, xa, xb, kb, row2);
        stile(Ws, wa, wb, kb, row2);
        __syncthreads();
        if (c < DIN / BK - 1) {
            const float* xn = xrow + (c + 1) * BK;
            const float* wn = wrow + (c + 1) * BK;
            xa = *(const float4*)xn; xb = *(const float4*)(xn + 4);
            wa = *(const float4*)wn; wb = *(const float4*)(wn + 4);
        }
#pragma unroll
        for (int k = 0; k < BK; k++) {
            float4 a0 = *(const float4*)(Xs + k * 128 + ty * 8);
            float4 a1 = *(const float4*)(Xs + k * 128 + ty * 8 + 4);
            float4 b0 = *(const float4*)(Ws + k * 128 + tx * 8);
            float4 b1 = *(const float4*)(Ws + k * 128 + tx * 8 + 4);
            MMA_STEP(a0, a1, b0, b1);
        }
    }

    // bias + relu, store H k-major into Hs with block swizzle:
    // phys = c*132 + 4*(((m>>2) + (c>>3)) & 31) + (m&3)
    {
        float bias1[8];
#pragma unroll
        for (int e = 0; e < 8; e++) bias1[e] = B1[tx * 8 + e];
#pragma unroll
        for (int i = 0; i < 8; i++) {
            const int m = ty * 8 + i;
            const int mb = ((m >> 2) + tx) & 31;   // (c>>3)==tx for this thread's cols
            const int po = (mb << 2) + (m & 3);
#pragma unroll
            for (int jp = 0; jp < 4; jp++) {
                float v0, v1; unpack2(acc[i][jp], v0, v1);
                v0 = fmaxf(v0 + bias1[2 * jp],     0.f);
                v1 = fmaxf(v1 + bias1[2 * jp + 1], 0.f);
                const int c0 = tx * 8 + 2 * jp;
                Hs[c0 * HS_STRIDE + po]       = v0;
                Hs[(c0 + 1) * HS_STRIDE + po] = v1;
            }
        }
    }

    // ---------------- Phase B: Y = H @ W2^T + b2, K = 128 -------------------
#pragma unroll
    for (int i = 0; i < 8; i++)
#pragma unroll
        for (int j = 0; j < 4; j++) acc[i][j] = 0ULL;

    for (int ch = 0; ch < Dm / BK; ch++) {
        __syncthreads();   // Hs ready (ch=0) / prev chunk done with Ws (ch>0)
        {
            const float* w2p = W2 + (size_t)row2 * Dm + ch * BK + kb;
            float4 va = *(const float4*)w2p;
            float4 vb = *(const float4*)(w2p + 4);
            stile(Ws, va, vb, kb, row2);
        }
        __syncthreads();
#pragma unroll
        for (int kk = 0; kk < BK; kk++) {
            const int k = ch * BK + kk;
            const int k3 = k >> 3;
            float4 a0 = *(const float4*)(Hs + k * HS_STRIDE + ((((2 * ty)     + k3) & 31) << 2));
            float4 a1 = *(const float4*)(Hs + k * HS_STRIDE + ((((2 * ty + 1) + k3) & 31) << 2));
            float4 b0 = *(const float4*)(Ws + kk * 128 + tx * 8);
            float4 b1 = *(const float4*)(Ws + kk * 128 + tx * 8 + 4);
            MMA_STEP(a0, a1, b0, b1);
        }
    }

    // bias + row L2-norm epilogue
    float ss[8];
    {
        float bias2[8];
#pragma unroll
        for (int e = 0; e < 8; e++) bias2[e] = B2[tx * 8 + e];
#pragma unroll
        for (int i = 0; i < 8; i++) {
            float s = 0.f;
#pragma unroll
            for (int jp = 0; jp < 4; jp++) {
                float v0, v1; unpack2(acc[i][jp], v0, v1);
                v0 += bias2[2 * jp]; v1 += bias2[2 * jp + 1];
                s += v0 * v0 + v1 * v1;
                acc[i][jp] = pack2(v0, v1);
            }
            ss[i] = s;
        }
    }
    __syncthreads();   // everyone done reading Ws/Hs -> reuse Xs/Ws region
#pragma unroll
    for (int i = 0; i < 8; i++) red[(ty * 8 + i) * 17 + tx] = ss[i];
    __syncthreads();
    if (t < 128) {
        float s = 0.f;
#pragma unroll
        for (int q = 0; q < 16; q++) s += red[t * 17 + q];
        rinv[t] = rsqrtf(s);
    }
    __syncthreads();
#pragma unroll
    for (int i = 0; i < 8; i++) {
        const float rv = rinv[ty * 8 + i];
        float v[8];
#pragma unroll
        for (int jp = 0; jp < 4; jp++) {
            float v0, v1; unpack2(acc[i][jp], v0, v1);
            v[2 * jp] = v0 * rv; v[2 * jp + 1] = v1 * rv;
        }
        float* op = OUT + (size_t)(rowbase + ty * 8 + i) * Dm + tx * 8;
        ((float4*)op)[0] = make_float4(v[0], v[1], v[2], v[3]);
        ((float4*)op)[1] = make_float4(v[4], v[5], v[6], v[7]);
    }
}

// ---------------------------------------------------------------------------
// Loss kernel: one block per b (12 warps = 12 patches).
// sym_kl(a,b) = sum_i (pa_i - pb_i)(la_i - lb_i), logits scaled by 1/T.
// ---------------------------------------------------------------------------
__device__ __forceinline__ float wredsum(float v) {
#pragma unroll
    for (int o = 16; o; o >>= 1) v += __shfl_xor_sync(0xffffffffu, v, o);
    return v;
}
__device__ __forceinline__ float wredmax(float v) {
#pragma unroll
    for (int o = 16; o; o >>= 1) v = fmaxf(v, __shfl_xor_sync(0xffffffffu, v, o));
    return v;
}

__device__ __forceinline__ float symkl4(const float* u, const float* v) {
    const float iT = 1.0f / T_KD;
    float uu[4], vv[4];
    float mu = -1e30f, mv = -1e30f;
#pragma unroll
    for (int q = 0; q < 4; q++) {
        uu[q] = u[q] * iT; vv[q] = v[q] * iT;
        mu = fmaxf(mu, uu[q]); mv = fmaxf(mv, vv[q]);
    }
    mu = wredmax(mu); mv = wredmax(mv);
    float eu[4], ev[4], su = 0.f, sv = 0.f;
#pragma unroll
    for (int q = 0; q < 4; q++) {
        eu[q] = __expf(uu[q] - mu); su += eu[q];
        ev[q] = __expf(vv[q] - mv); sv += ev[q];
    }
    su = wredsum(su); sv = wredsum(sv);
    const float lsu = __logf(su), lsv = __logf(sv);
    const float isu = 1.f / su,  isv = 1.f / sv;
    float a = 0.f;
#pragma unroll
    for (int q = 0; q < 4; q++) {
        const float la = uu[q] - mu - lsu;
        const float lb = vv[q] - mv - lsv;
        a += (eu[q] * isu - ev[q] * isv) * (la - lb);
    }
    return wredsum(a);
}

__global__ void __launch_bounds__(384) loss_kernel() {
    __shared__ float parr[Pn][Dm];
    __shared__ float gs[Dm], pbs[Dm];
    __shared__ float wsum[Pn + 1];

    const int b    = blockIdx.x;
    const int t    = threadIdx.x;
    const int w    = t >> 5;
    const int lane = t & 31;

    // each warp loads its patch row
    {
        float4 pv = *(const float4*)(p_buf + ((size_t)w * Bsz + b) * Dm + lane * 4);
        *(float4*)(&parr[w][lane * 4]) = pv;
        if (w == 0) {
            float4 gv = *(const float4*)(g_buf + (size_t)b * Dm + lane * 4);
            *(float4*)(&gs[lane * 4]) = gv;
        }
    }
    __syncthreads();
    if (t < Dm) {
        float s = 0.f;
#pragma unroll
        for (int l = 0; l < Pn; l++) s += parr[l][t];
        pbs[t] = s * (1.0f / Pn);
    }
    __syncthreads();

    // dcl contribution of this (b, w)
    float du[4], dv[4];
#pragma unroll
    for (int q = 0; q < 4; q++) {
        const int c = lane * 4 + q;
        const float pv = parr[w][c];
        float a = gs[c]  - pv; du[q] = a * a;
        float d = pbs[c] - pv; dv[q] = d * d;
    }
    const float vdcl = symkl4(du, dv);
    if (lane == 0) wsum[w] = vdcl;

    if (w == 0) {   // dil for this b
        float u[4], v[4];
#pragma unroll
        for (int q = 0; q < 4; q++) {
            u[q] = gs[lane * 4 + q];
            v[q] = pbs[lane * 4 + q];
        }
        const float vdil = symkl4(u, v);
        if (lane == 0) wsum[Pn] = vdil;
    }
    __syncthreads();
    if (t == 0) {
        float dcl = 0.f;
#pragma unroll
        for (int l = 0; l < Pn; l++) dcl += wsum[l];
        const float sc = (T_KD * T_KD) / (float)Dm;
        part_dcl[b] = dcl * sc;
        part_dil[b] = wsum[Pn] * sc;
    }
}

// Deterministic fixed-order final reduction
__global__ void __launch_bounds__(256) final_kernel(float* out, int out_size) {
    __shared__ float s1[256], s2[256];
    const int t = threadIdx.x;
    float a = 0.f, c = 0.f;
    for (int i = t; i < Bsz; i += 256) { a += part_dil[i]; c += part_dcl[i]; }
    s1[t] = a; s2[t] = c;
    __syncthreads();
#pragma unroll
    for (int o = 128; o > 0; o >>= 1) {
        if (t < o) { s1[t] += s1[t + o]; s2[t] += s2[t + o]; }
        __syncthreads();
    }
    if (t == 0) {
        if (out_size > 0) out[0] = s1[0];
        if (out_size > 1) out[1] = s2[0] * (1.0f / Pn);
    }
}

extern "C" void kernel_launch(void* const* d_in, const int* in_sizes, int n_in,
                              void* d_out, int out_size) {
    (void)in_sizes; (void)n_in;
    const float* ebg = (const float*)d_in[0];
    const float* ebp = (const float*)d_in[1];
    // d_in[2] = labelsg (unused by the forward losses)
    const float* gw1 = (const float*)d_in[3];
    const float* gb1 = (const float*)d_in[4];
    const float* gw2 = (const float*)d_in[5];
    const float* gb2 = (const float*)d_in[6];
    const float* pw1 = (const float*)d_in[7];
    const float* pb1 = (const float*)d_in[8];
    const float* pw2 = (const float*)d_in[9];
    const float* pb2 = (const float*)d_in[10];

    // idempotent; ignore return (harmless if repeated under capture)
    cudaFuncSetAttribute(embed_kernel,
                         cudaFuncAttributeMaxDynamicSharedMemorySize, SMEM_BYTES);

    embed_kernel<<<NBLK_G + NBLK_P, 256, SMEM_BYTES>>>(
        ebg, ebp, gw1, gb1, gw2, gb2, pw1, pb1, pw2, pb2);
    loss_kernel<<<Bsz, 384>>>();
    final_kernel<<<1, 256>>>((float*)d_out, out_size);
}

// round 2
// speedup vs baseline: 1.0869x; 1.0869x over previous
#include <cuda_runtime.h>

// ---------------------------------------------------------------------------
// Sup_CCL_Loss: fused MLP embed (640->128 relu 128->128, L2 norm) for global
// and patch streams, then symmetric-KL losses (dil, dcl).
// R2: conflict-free XOR-swizzled staging tiles, single-barrier double
// buffering, persistent 2-blocks/SM grid.
// ---------------------------------------------------------------------------

#define T_KD   4.0f
#define Bsz    4096
#define Pn     12
#define DIN    640
#define Dm     128

#define BM     128
#define BK     16
#define NBLK_G (Bsz / BM)          // 32
#define NBLK_P (Pn * Bsz / BM)     // 384
#define NTILES (NBLK_G + NBLK_P)   // 416
#define NPERS  296                 // 2 blocks per SM * 148 SMs
#define HS_STRIDE 132
// Hs + 2 stages of (X tile + W tile), each tile BK*128 floats
#define STAGE_F   (BK * 128)                         // 2048
#define SMEM_FLOATS (128 * HS_STRIDE + 4 * STAGE_F)  // 16896 + 8192
#define SMEM_BYTES  (SMEM_FLOATS * 4)                // 100352

// Scratch (static device arrays: allowed; no cudaMalloc anywhere)
__device__ float g_buf[Bsz * Dm];
__device__ float p_buf[Pn * Bsz * Dm];
__device__ float part_dil[Bsz];
__device__ float part_dcl[Bsz];

typedef unsigned long long u64;

__device__ __forceinline__ u64 dup2(float v) {
    u64 r; asm("mov.b64 %0,{%1,%1};" : "=l"(r) : "f"(v)); return r;
}
__device__ __forceinline__ u64 pack2(float lo, float hi) {
    u64 r; asm("mov.b64 %0,{%1,%2};" : "=l"(r) : "f"(lo), "f"(hi)); return r;
}
__device__ __forceinline__ void unpack2(u64 v, float& lo, float& hi) {
    asm("mov.b64 {%0,%1},%2;" : "=f"(lo), "=f"(hi) : "l"(v));
}
__device__ __forceinline__ void fma2(u64& d, u64 a, u64 b) {
    asm("fma.rn.f32x2 %0,%1,%2,%3;" : "=l"(d) : "l"(a), "l"(b), "l"(d));
}

// bank swizzle: move odd 32B chunks into free 16B slots -> conflict-free
// strided 32B reads. Granularity 4 floats, so float4 loads stay contiguous.
__device__ __forceinline__ int swz(int i) { return i ^ ((i & 32) >> 3); }

// one k-step of the 8x8 (as 8x4 packed) outer product
#define MMA_STEP(A0, A1, B0, B1) do {                                        \
    u64 bp0 = pack2((B0).x, (B0).y), bp1 = pack2((B0).z, (B0).w);            \
    u64 bp2 = pack2((B1).x, (B1).y), bp3 = pack2((B1).z, (B1).w);            \
    float av[8] = {(A0).x,(A0).y,(A0).z,(A0).w,(A1).x,(A1).y,(A1).z,(A1).w}; \
    _Pragma("unroll")                                                        \
    for (int ii = 0; ii < 8; ii++) {                                         \
        u64 ad = dup2(av[ii]);                                               \
        fma2(acc[ii][0], ad, bp0); fma2(acc[ii][1], ad, bp1);                \
        fma2(acc[ii][2], ad, bp2); fma2(acc[ii][3], ad, bp3);                \
    }                                                                        \
} while (0)

// transpose-store a 2x float4 strip into a k-major tile [BK][128], swizzled col
__device__ __forceinline__ void stile(float* S, float4 a, float4 b, int kb, int rp) {
    S[(kb + 0) * 128 + rp] = a.x; S[(kb + 1) * 128 + rp] = a.y;
    S[(kb + 2) * 128 + rp] = a.z; S[(kb + 3) * 128 + rp] = a.w;
    S[(kb + 4) * 128 + rp] = b.x; S[(kb + 5) * 128 + rp] = b.y;
    S[(kb + 6) * 128 + rp] = b.z; S[(kb + 7) * 128 + rp] = b.w;
}

__global__ void __launch_bounds__(256, 2) embed_kernel(
    const float* __restrict__ ebg, const float* __restrict__ ebp,
    const float* __restrict__ gw1, const float* __restrict__ gb1,
    const float* __restrict__ gw2, const float* __restrict__ gb2,
    const float* __restrict__ pw1, const float* __restrict__ pb1,
    const float* __restrict__ pw2, const float* __restrict__ pb2)
{
    extern __shared__ float sm[];
    float* Hs  = sm;                      // [128][132], k-major, block-swizzled
    float* stg = sm + 128 * HS_STRIDE;    // 2 stages x (X[16x128], W[16x128])
    float* red  = stg;                    // epilogue reuse, stride 17
    float* rinv = stg + 128 * 17;         // epilogue reuse

    const int t  = threadIdx.x;
    const int tx = t & 15;
    const int ty = t >> 4;
    const int row2 = t >> 1;          // 0..127 (loader row)
    const int kb   = (t & 1) * 8;     // loader k-offset
    const int rp   = swz(row2);       // swizzled store column

    // swizzle-adjusted read base offsets (constant per thread)
    const int bo0 = swz(tx * 8), bo1 = swz(tx * 8 + 4);
    const int ao0 = swz(ty * 8), ao1 = swz(ty * 8 + 4);

    for (int blk = blockIdx.x; blk < NTILES; blk += gridDim.x) {
        const float *X, *W1, *B1, *W2, *B2;
        float* OUT;
        int rowbase;
        if (blk < NBLK_G) {
            X = ebg; W1 = gw1; B1 = gb1; W2 = gw2; B2 = gb2;
            OUT = g_buf; rowbase = blk * BM;
        } else {
            X = ebp; W1 = pw1; B1 = pb1; W2 = pw2; B2 = pb2;
            OUT = p_buf; rowbase = (blk - NBLK_G) * BM;
        }

        u64 acc[8][4];
#pragma unroll
        for (int i = 0; i < 8; i++)
#pragma unroll
            for (int j = 0; j < 4; j++) acc[i][j] = 0ULL;

        // ------------- Phase A: H = relu(X @ W1^T + b1), K = 640 ------------
        const float* xrow = X  + (size_t)(rowbase + row2) * DIN + kb;
        const float* wrow = W1 + (size_t)row2 * DIN + kb;
        float4 xa = *(const float4*)xrow, xb = *(const float4*)(xrow + 4);
        float4 wa = *(const float4*)wrow, wb = *(const float4*)(wrow + 4);
        stile(stg,           xa, xb, kb, rp);
        stile(stg + STAGE_F, wa, wb, kb, rp);
        __syncthreads();

#pragma unroll 1
        for (int c = 0; c < DIN / BK; c++) {
            if (c < DIN / BK - 1) {
                const float* xn = xrow + (c + 1) * BK;
                const float* wn = wrow + (c + 1) * BK;
                xa = *(const float4*)xn; xb = *(const float4*)(xn + 4);
                wa = *(const float4*)wn; wb = *(const float4*)(wn + 4);
            }
            const float* Xc = stg + ((c & 1) << 12);
            const float* Wc = Xc + STAGE_F;
#pragma unroll
            for (int k = 0; k < BK; k++) {
                float4 a0 = *(const float4*)(Xc + k * 128 + ao0);
                float4 a1 = *(const float4*)(Xc + k * 128 + ao1);
                float4 b0 = *(const float4*)(Wc + k * 128 + bo0);
                float4 b1 = *(const float4*)(Wc + k * 128 + bo1);
                MMA_STEP(a0, a1, b0, b1);
            }
            if (c < DIN / BK - 1) {
                float* Xn = stg + (((c + 1) & 1) << 12);
                stile(Xn,           xa, xb, kb, rp);
                stile(Xn + STAGE_F, wa, wb, kb, rp);
            }
            __syncthreads();
        }

        // bias + relu, store H k-major into Hs with block swizzle:
        // phys = c*132 + 4*(((m>>2) + (c>>3)) & 31) + (m&3)
        {
            float bias1[8];
#pragma unroll
            for (int e = 0; e < 8; e++) bias1[e] = B1[tx * 8 + e];
#pragma unroll
            for (int i = 0; i < 8; i++) {
                const int m = ty * 8 + i;
                const int mb = ((m >> 2) + tx) & 31;   // (c>>3)==tx here
                const int po = (mb << 2) + (m & 3);
#pragma unroll
                for (int jp = 0; jp < 4; jp++) {
                    float v0, v1; unpack2(acc[i][jp], v0, v1);
                    v0 = fmaxf(v0 + bias1[2 * jp],     0.f);
                    v1 = fmaxf(v1 + bias1[2 * jp + 1], 0.f);
                    const int c0 = tx * 8 + 2 * jp;
                    Hs[c0 * HS_STRIDE + po]       = v0;
                    Hs[(c0 + 1) * HS_STRIDE + po] = v1;
                }
            }
        }

        // ------------- Phase B: Y = H @ W2^T + b2, K = 128 ------------------
#pragma unroll
        for (int i = 0; i < 8; i++)
#pragma unroll
            for (int j = 0; j < 4; j++) acc[i][j] = 0ULL;

        const float* w2row = W2 + (size_t)row2 * Dm + kb;
        wa = *(const float4*)w2row; wb = *(const float4*)(w2row + 4);
        stile(stg + STAGE_F, wa, wb, kb, rp);
        __syncthreads();   // Hs ready + stage0 W ready

#pragma unroll 1
        for (int ch = 0; ch < Dm / BK; ch++) {
            if (ch < Dm / BK - 1) {
                const float* wn = w2row + (ch + 1) * BK;
                wa = *(const float4*)wn; wb = *(const float4*)(wn + 4);
            }
            const float* Wc = stg + ((ch & 1) << 12) + STAGE_F;
#pragma unroll
            for (int kk = 0; kk < BK; kk++) {
                const int k = ch * BK + kk;
                const int k3 = k >> 3;
                float4 a0 = *(const float4*)(Hs + k * HS_STRIDE + ((((2 * ty)     + k3) & 31) << 2));
                float4 a1 = *(const float4*)(Hs + k * HS_STRIDE + ((((2 * ty + 1) + k3) & 31) << 2));
                float4 b0 = *(const float4*)(Wc + kk * 128 + bo0);
                float4 b1 = *(const float4*)(Wc + kk * 128 + bo1);
                MMA_STEP(a0, a1, b0, b1);
            }
            if (ch < Dm / BK - 1) {
                stile(stg + (((ch + 1) & 1) << 12) + STAGE_F, wa, wb, kb, rp);
            }
            __syncthreads();
        }

        // bias + row L2-norm epilogue
        float ss[8];
        {
            float bias2[8];
#pragma unroll
            for (int e = 0; e < 8; e++) bias2[e] = B2[tx * 8 + e];
#pragma unroll
            for (int i = 0; i < 8; i++) {
                float s = 0.f;
#pragma unroll
                for (int jp = 0; jp < 4; jp++) {
                    float v0, v1; unpack2(acc[i][jp], v0, v1);
                    v0 += bias2[2 * jp]; v1 += bias2[2 * jp + 1];
                    s += v0 * v0 + v1 * v1;
                    acc[i][jp] = pack2(v0, v1);
                }
                ss[i] = s;
            }
        }
        // stage buffers are free after the last loop barrier
#pragma unroll
        for (int i = 0; i < 8; i++) red[(ty * 8 + i) * 17 + tx] = ss[i];
        __syncthreads();
        if (t < 128) {
            float s = 0.f;
#pragma unroll
            for (int q = 0; q < 16; q++) s += red[t * 17 + q];
            rinv[t] = rsqrtf(s);
        }
        __syncthreads();
#pragma unroll
        for (int i = 0; i < 8; i++) {
            const float rv = rinv[ty * 8 + i];
            float v[8];
#pragma unroll
            for (int jp = 0; jp < 4; jp++) {
                float v0, v1; unpack2(acc[i][jp], v0, v1);
                v[2 * jp] = v0 * rv; v[2 * jp + 1] = v1 * rv;
            }
            float* op = OUT + (size_t)(rowbase + ty * 8 + i) * Dm + tx * 8;
            ((float4*)op)[0] = make_float4(v[0], v[1], v[2], v[3]);
            ((float4*)op)[1] = make_float4(v[4], v[5], v[6], v[7]);
        }
        __syncthreads();   // protect stg/Hs before next tile
    }
}

// ---------------------------------------------------------------------------
// Loss kernel: one block per b (12 warps = 12 patches).
// sym_kl(a,b) = sum_i (pa_i - pb_i)(la_i - lb_i), logits scaled by 1/T.
// ---------------------------------------------------------------------------
__device__ __forceinline__ float wredsum(float v) {
#pragma unroll
    for (int o = 16; o; o >>= 1) v += __shfl_xor_sync(0xffffffffu, v, o);
    return v;
}
__device__ __forceinline__ float wredmax(float v) {
#pragma unroll
    for (int o = 16; o; o >>= 1) v = fmaxf(v, __shfl_xor_sync(0xffffffffu, v, o));
    return v;
}

__device__ __forceinline__ float symkl4(const float* u, const float* v) {
    const float iT = 1.0f / T_KD;
    float uu[4], vv[4];
    float mu = -1e30f, mv = -1e30f;
#pragma unroll
    for (int q = 0; q < 4; q++) {
        uu[q] = u[q] * iT; vv[q] = v[q] * iT;
        mu = fmaxf(mu, uu[q]); mv = fmaxf(mv, vv[q]);
    }
    mu = wredmax(mu); mv = wredmax(mv);
    float eu[4], ev[4], su = 0.f, sv = 0.f;
#pragma unroll
    for (int q = 0; q < 4; q++) {
        eu[q] = __expf(uu[q] - mu); su += eu[q];
        ev[q] = __expf(vv[q] - mv); sv += ev[q];
    }
    su = wredsum(su); sv = wredsum(sv);
    const float lsu = __logf(su), lsv = __logf(sv);
    const float isu = 1.f / su,  isv = 1.f / sv;
    float a = 0.f;
#pragma unroll
    for (int q = 0; q < 4; q++) {
        const float la = uu[q] - mu - lsu;
        const float lb = vv[q] - mv - lsv;
        a += (eu[q] * isu - ev[q] * isv) * (la - lb);
    }
    return wredsum(a);
}

__global__ void __launch_bounds__(384) loss_kernel() {
    __shared__ float parr[Pn][Dm];
    __shared__ float gs[Dm], pbs[Dm];
    __shared__ float wsum[Pn + 1];

    const int b    = blockIdx.x;
    const int t    = threadIdx.x;
    const int w    = t >> 5;
    const int lane = t & 31;

    // each warp loads its patch row
    {
        float4 pv = *(const float4*)(p_buf + ((size_t)w * Bsz + b) * Dm + lane * 4);
        *(float4*)(&parr[w][lane * 4]) = pv;
        if (w == 0) {
            float4 gv = *(const float4*)(g_buf + (size_t)b * Dm + lane * 4);
            *(float4*)(&gs[lane * 4]) = gv;
        }
    }
    __syncthreads();
    if (t < Dm) {
        float s = 0.f;
#pragma unroll
        for (int l = 0; l < Pn; l++) s += parr[l][t];
        pbs[t] = s * (1.0f / Pn);
    }
    __syncthreads();

    // dcl contribution of this (b, w)
    float du[4], dv[4];
#pragma unroll
    for (int q = 0; q < 4; q++) {
        const int c = lane * 4 + q;
        const float pv = parr[w][c];
        float a = gs[c]  - pv; du[q] = a * a;
        float d = pbs[c] - pv; dv[q] = d * d;
    }
    const float vdcl = symkl4(du, dv);
    if (lane == 0) wsum[w] = vdcl;

    if (w == 0) {   // dil for this b
        float u[4], v[4];
#pragma unroll
        for (int q = 0; q < 4; q++) {
            u[q] = gs[lane * 4 + q];
            v[q] = pbs[lane * 4 + q];
        }
        const float vdil = symkl4(u, v);
        if (lane == 0) wsum[Pn] = vdil;
    }
    __syncthreads();
    if (t == 0) {
        float dcl = 0.f;
#pragma unroll
        for (int l = 0; l < Pn; l++) dcl += wsum[l];
        const float sc = (T_KD * T_KD) / (float)Dm;
        part_dcl[b] = dcl * sc;
        part_dil[b] = wsum[Pn] * sc;
    }
}

// Deterministic fixed-order final reduction
__global__ void __launch_bounds__(256) final_kernel(float* out, int out_size) {
    __shared__ float s1[256], s2[256];
    const int t = threadIdx.x;
    float a = 0.f, c = 0.f;
    for (int i = t; i < Bsz; i += 256) { a += part_dil[i]; c += part_dcl[i]; }
    s1[t] = a; s2[t] = c;
    __syncthreads();
#pragma unroll
    for (int o = 128; o > 0; o >>= 1) {
        if (t < o) { s1[t] += s1[t + o]; s2[t] += s2[t + o]; }
        __syncthreads();
    }
    if (t == 0) {
        if (out_size > 0) out[0] = s1[0];
        if (out_size > 1) out[1] = s2[0] * (1.0f / Pn);
    }
}

extern "C" void kernel_launch(void* const* d_in, const int* in_sizes, int n_in,
                              void* d_out, int out_size) {
    (void)in_sizes; (void)n_in;
    const float* ebg = (const float*)d_in[0];
    const float* ebp = (const float*)d_in[1];
    // d_in[2] = labelsg (unused by the forward losses)
    const float* gw1 = (const float*)d_in[3];
    const float* gb1 = (const float*)d_in[4];
    const float* gw2 = (const float*)d_in[5];
    const float* gb2 = (const float*)d_in[6];
    const float* pw1 = (const float*)d_in[7];
    const float* pb1 = (const float*)d_in[8];
    const float* pw2 = (const float*)d_in[9];
    const float* pb2 = (const float*)d_in[10];

    cudaFuncSetAttribute(embed_kernel,
                         cudaFuncAttributeMaxDynamicSharedMemorySize, SMEM_BYTES);

    embed_kernel<<<NPERS, 256, SMEM_BYTES>>>(
        ebg, ebp, gw1, gb1, gw2, gb2, pw1, pb1, pw2, pb2);
    loss_kernel<<<Bsz, 384>>>();
    final_kernel<<<1, 256>>>((float*)d_out, out_size);
}